// round 8
// baseline (speedup 1.0000x reference)
#include <cuda_runtime.h>
#include <cstdint>

#define NB    2
#define NA    9
#define NHW   4096        // 64*64
#define NPROP 36864       // NHW*NA
#define NPAD  65536
#define TOPN  2000
#define WIN   1024        // candidates per window
#define WRD   16          // 64-bit words per window
#define NWIN  36          // WIN*NWIN = NPROP
#define BLKB  64          // persistent blocks per batch
#define PROWIN 24         // windows masked in prologue; rest on-demand

typedef unsigned long long u64;

// Anchors from generate_anchors(16,(0.5,1,2),(8,16,32)) with base [0,0,15,15].
__constant__ float c_anchors[9][4] = {
  { -84.f,  -40.f,  99.f,  55.f},
  {-176.f,  -88.f, 191.f, 103.f},
  {-360.f, -184.f, 375.f, 199.f},
  { -56.f,  -56.f,  71.f,  71.f},
  {-120.f, -120.f, 135.f, 135.f},
  {-248.f, -248.f, 263.f, 263.f},
  { -36.f,  -80.f,  51.f,  95.f},
  { -80.f, -168.f,  95.f, 183.f},
  {-168.f, -344.f, 183.f, 359.f}
};

__device__ float4 g_boxes [NB][NPROP];
__device__ float  g_scores[NB][NPROP];
__device__ u64    g_keys  [NB * NPAD];
__device__ float4 g_sbox  [NB][NPROP];
__device__ float  g_sscore[NB][NPROP];
__device__ float  g_sarea [NB][NPROP];
__device__ u64    g_awmask[NB][NWIN][WRD][WIN]; // in-window masks (9.4MB)
__device__ u64    g_remwAll[NB][NWIN][WRD];     // per-window kept suppression
__device__ float4 g_kbox  [NB][TOPN];
__device__ float  g_karea [NB][TOPN];
__device__ int    g_keptIdx[NB][TOPN];
__device__ int    g_keptCnt[NB];
__device__ int    g_kc[NB][2];                  // ping-pong published count
__device__ int    g_done  [NB];
__device__ unsigned g_barcnt[NB];
__device__ unsigned g_bargen[NB];

// per-batch software barrier across BLKB co-resident blocks (spin on load)
__device__ __forceinline__ void bbar(int b, int gen)
{
    __syncthreads();
    if (threadIdx.x == 0) {
        __threadfence();
        unsigned arrive = atomicAdd(&g_barcnt[b], 1u) + 1u;
        if (arrive == (unsigned)BLKB * (unsigned)gen) {
            atomicExch(&g_bargen[b], (unsigned)gen);
        } else {
            while (*(volatile unsigned*)&g_bargen[b] < (unsigned)gen) { }
        }
        __threadfence();
    }
    __syncthreads();
}

// IoU>0.7 bits of box (bi,ai) vs 64 smem boxes starting at wb.
// Branch-free band + exact __fdiv_rn resolution (reference op order).
__device__ __forceinline__ u64 iou_word(float4 bi, float ai,
                                        const float4* cbx, const float* car,
                                        int wb)
{
    u64 bsup = 0, bamb = 0;
#pragma unroll 8
    for (int j2 = 0; j2 < 64; j2++) {
        float4 bj = cbx[wb + j2];
        float  aj = car[wb + j2];
        float iw = fmaxf(__fadd_rn(__fsub_rn(fminf(bi.z, bj.z), fmaxf(bi.x, bj.x)), 1.0f), 0.0f);
        float ih = fmaxf(__fadd_rn(__fsub_rn(fminf(bi.w, bj.w), fmaxf(bi.y, bj.y)), 1.0f), 0.0f);
        float inter = __fmul_rn(iw, ih);
        float s     = __fadd_rn(ai, aj);
        bool hi = inter > __fmul_rn(s, 0.411775f);
        bool lo = inter < __fmul_rn(s, 0.411755f);
        bsup |= ((u64)hi) << j2;
        bamb |= ((u64)(!hi && !lo)) << j2;
    }
    while (bamb) {
        int j2 = __ffsll((long long)bamb) - 1;
        bamb &= bamb - 1;
        float4 bj = cbx[wb + j2];
        float iw = fmaxf(__fadd_rn(__fsub_rn(fminf(bi.z, bj.z), fmaxf(bi.x, bj.x)), 1.0f), 0.0f);
        float ih = fmaxf(__fadd_rn(__fsub_rn(fminf(bi.w, bj.w), fmaxf(bi.y, bj.y)), 1.0f), 0.0f);
        float inter = __fmul_rn(iw, ih);
        float s     = __fadd_rn(ai, car[wb + j2]);
        float denom = __fsub_rn(s, inter);
        if (__fdiv_rn(inter, denom) > 0.7f) bsup |= (1ull << j2);
    }
    return bsup;
}

// ---------------------------------------------------------------- prep ----
__global__ __launch_bounds__(256) void k_prep(const float* __restrict__ sm,
                                              const float* __restrict__ bd,
                                              const float* __restrict__ img)
{
    int b = blockIdx.y;
    int i = blockIdx.x * 256 + threadIdx.x;       // 0..NPAD-1
    if (i == 0) {
        g_done[b] = 0; g_keptCnt[b] = 0;
        g_kc[b][0] = 0; g_kc[b][1] = 0;
        g_barcnt[b] = 0; g_bargen[b] = 0;
    }
    if (i < NWIN * WRD) g_remwAll[b][i >> 4][i & 15] = 0;
    if (i >= NPAD) return;
    if (i >= NPROP) { g_keys[b * NPAD + i] = ~0ull; return; }

    int a  = i % NA;
    int hw = i / NA;
    float cx = (float)((hw & 63) * 16 + 8);
    float cy = (float)((hw >> 6) * 16 + 8);

    float ax1 = cx + c_anchors[a][0];
    float ay1 = cy + c_anchors[a][1];
    float ax2 = cx + c_anchors[a][2];
    float ay2 = cy + c_anchors[a][3];

    float wA = ax2 - ax1 + 1.0f;                  // exact small integers
    float hA = ay2 - ay1 + 1.0f;
    float ctrx = __fadd_rn(ax1, __fmul_rn(0.5f, wA));
    float ctry = __fadd_rn(ay1, __fmul_rn(0.5f, hA));

    const float* bdb = bd + ((size_t)b * 36 + (size_t)a * 4) * NHW + hw;
    float dx = bdb[0];
    float dy = bdb[NHW];
    float dw = bdb[2 * NHW];
    float dh = bdb[3 * NHW];

    // reference op order: mul then add, no contraction
    float pcx = __fadd_rn(__fmul_rn(dx, wA), ctrx);
    float pcy = __fadd_rn(__fmul_rn(dy, hA), ctry);
    float pw  = __fmul_rn(expf(dw), wA);
    float ph  = __fmul_rn(expf(dh), hA);

    float x1 = __fsub_rn(pcx, __fmul_rn(0.5f, pw));
    float y1 = __fsub_rn(pcy, __fmul_rn(0.5f, ph));
    float x2 = __fadd_rn(pcx, __fmul_rn(0.5f, pw));
    float y2 = __fadd_rn(pcy, __fmul_rn(0.5f, ph));

    float imh = img[b * 3 + 0];
    float imw = img[b * 3 + 1];
    float mx  = __fsub_rn(imw, 1.0f);
    float my  = __fsub_rn(imh, 1.0f);
    x1 = fminf(fmaxf(x1, 0.0f), mx);
    x2 = fminf(fmaxf(x2, 0.0f), mx);
    y1 = fminf(fmaxf(y1, 0.0f), my);
    y2 = fminf(fmaxf(y2, 0.0f), my);

    float s = sm[((size_t)b * 18 + 9 + a) * NHW + hw];

    g_boxes[b][i]  = make_float4(x1, y1, x2, y2);
    g_scores[b][i] = s;

    unsigned u = __float_as_uint(s);
    unsigned k = (u & 0x80000000u) ? ~u : (u | 0x80000000u);  // ascending
    unsigned kd = ~k;                                          // descending
    g_keys[b * NPAD + i] = ((u64)kd << 32) | (unsigned)i;
}

// ---------------------------------------------------------------- sort ----
// 8192-element chunks in 64KB dynamic smem (16 blocks). Canonical bitonic:
// ascending iff ((li & len) == 0).
__global__ __launch_bounds__(1024) void k_sort_local(int startLen)
{
    extern __shared__ u64 sk[];
    int base = blockIdx.x * 8192;                 // flat over NB*NPAD
    int tid  = threadIdx.x;

#pragma unroll
    for (int e = 0; e < 8; e++) sk[e * 1024 + tid] = g_keys[base + e * 1024 + tid];
    __syncthreads();

    if (startLen == 0) {
        for (int len = 2; len <= 8192; len <<= 1) {
            for (int d = len >> 1; d > 0; d >>= 1) {
#pragma unroll
                for (int e = 0; e < 4; e++) {
                    int idx = e * 1024 + tid;          // 0..4095 pair ids
                    int i = ((idx & ~(d - 1)) << 1) | (idx & (d - 1));
                    int j = i | d;
                    int li = (base + i) & (NPAD - 1);
                    bool asc = ((li & len) == 0);
                    u64 a = sk[i], c = sk[j];
                    if ((a > c) == asc) { sk[i] = c; sk[j] = a; }
                }
                __syncthreads();
            }
        }
    } else {
        bool asc = (((base & (NPAD - 1)) & startLen) == 0);
        for (int d = 4096; d > 0; d >>= 1) {
#pragma unroll
            for (int e = 0; e < 4; e++) {
                int idx = e * 1024 + tid;
                int i = ((idx & ~(d - 1)) << 1) | (idx & (d - 1));
                int j = i | d;
                u64 a = sk[i], c = sk[j];
                if ((a > c) == asc) { sk[i] = c; sk[j] = a; }
            }
            __syncthreads();
        }
    }

#pragma unroll
    for (int e = 0; e < 8; e++) g_keys[base + e * 1024 + tid] = sk[e * 1024 + tid];
}

__global__ __launch_bounds__(256) void k_sort_global(int len, int d)
{
    int i = blockIdx.x * 256 + threadIdx.x;       // flat element index
    if (i >= NB * NPAD) return;
    int li = i & (NPAD - 1);
    if (li & d) return;
    int j = i + d;                                 // same batch since (li&d)==0
    bool asc = ((li & len) == 0);
    u64 a = g_keys[i], c = g_keys[j];
    if ((a > c) == asc) { g_keys[i] = c; g_keys[j] = a; }
}

// -------------------------------------------------------------- gather ----
__global__ __launch_bounds__(256) void k_gather()
{
    int b = blockIdx.y;
    int p = blockIdx.x * 256 + threadIdx.x;
    if (p >= NPROP) return;
    unsigned idx = (unsigned)(g_keys[b * NPAD + p] & 0xFFFFFFFFull);
    float4 bx = g_boxes[b][idx];
    g_sbox[b][p]   = bx;
    g_sscore[b][p] = g_scores[b][idx];
    g_sarea[b][p]  = __fmul_rn(__fadd_rn(__fsub_rn(bx.z, bx.x), 1.0f),
                               __fadd_rn(__fsub_rn(bx.w, bx.y), 1.0f));
}

// ------------------------------------------------- persistent NMS loop ----
// grid (BLKB, NB), 512 threads, 148KB dyn smem (1 block/SM, co-resident).
// Prologue: in-window masks for windows 0..PROWIN-1.
// Iteration k (ONE barrier at end):
//   block 0:    rem = g_remwAll[k] | (new keeps of window k-1 vs window k),
//               then resolve window k entirely in smem; publish keeps.
//   blocks 1-32: kept(through k-1) vs window k+1 -> g_remwAll[k+1].
//   blocks 33-48: on-demand in-window mask of window k+1 (if k+1>=PROWIN).
__global__ __launch_bounds__(512) void k_nms()
{
    int b = blockIdx.y;
    int r = blockIdx.x;                // 0..BLKB-1
    int t = threadIdx.x;
    int rl = t & 63;
    int cg = t >> 6;                   // 0..7, two words each

    extern __shared__ char dynsmem[];
    u64*    blk = (u64*)dynsmem;                       // 128KB (resolve)
    float4* cbx = (float4*)(dynsmem + 131072);         // 16KB
    float*  car = (float*)(dynsmem + 131072 + 16384);  // 4KB

    __shared__ u64 red[WRD];
    __shared__ u64 rem[WRD];
    __shared__ short ckeptL[WIN];
    __shared__ int s_kept, s_nk, s_nkc, s_done, s_dlo, s_dhi, s_k0;

    if (t == 0) { s_kept = 0; s_dlo = 0; s_dhi = 0; }

    // ---- prologue: in-window masks for windows 0..PROWIN-1 ----
    for (int rg = r; rg < PROWIN * 16; rg += BLKB) {
        int k  = rg >> 4;
        int rb = rg & 15;
        for (int j = t; j < WIN; j += 512) {
            cbx[j] = g_sbox[b][k * WIN + j];
            car[j] = g_sarea[b][k * WIN + j];
        }
        __syncthreads();
        int i = k * WIN + rb * 64 + rl;
        float4 bi = g_sbox[b][i];
        float  ai = g_sarea[b][i];
#pragma unroll
        for (int ww = 0; ww < 2; ww++) {
            int w = cg * 2 + ww;
            u64 v = iou_word(bi, ai, cbx, car, w * 64);
            if (w == rb) v &= (rl == 63) ? 0ull : (~0ull << (rl + 1));
            g_awmask[b][k][w][rb * 64 + rl] = v;
        }
        __syncthreads();
    }

    int gen = 1;
    bbar(b, gen++);

    // ---- pipelined window loop ----
    for (int k = 0; k < NWIN; k++) {
        int kn = k + 1;
        if (r == 0) {
            // load window k columns + mask + base suppression
            for (int j = t; j < WIN; j += 512) {
                cbx[j] = g_sbox[b][k * WIN + j];
                car[j] = g_sarea[b][k * WIN + j];
            }
            const ulonglong2* src = (const ulonglong2*)&g_awmask[b][k][0][0];
            ulonglong2* dst = (ulonglong2*)blk;
#pragma unroll
            for (int q = 0; q < WRD; q++) dst[q * 512 + t] = src[q * 512 + t];
            if (t < WRD) rem[t] = g_remwAll[b][k][t];
            if (t == 0) { s_k0 = s_kept; s_done = 0; s_nkc = 0; }
            __syncthreads();

            // delta: keeps found in window k-1 vs window k
            for (int q = s_dlo + (t >> 4); q < s_dhi; q += 32) {
                float4 bi = g_kbox[b][q];
                float  ai = g_karea[b][q];
                u64 v = iou_word(bi, ai, cbx, car, (t & 15) * 64);
                if (v) atomicOr(&rem[t & 15], v);
            }
            __syncthreads();

            // resolve window k in smem
            for (int wl = 0; wl < WRD; wl++) {
                if (t == 0) {
                    u64 alive = ~rem[wl];
                    int nk = 0, kept = s_kept, nkc = s_nkc;
                    while (alive && kept < TOPN) {
                        int j = __ffsll((long long)alive) - 1;
                        int lr = wl * 64 + j;
                        g_keptIdx[b][kept++] = k * WIN + lr;
                        ckeptL[nkc++] = (short)lr;
                        nk++;
                        alive &= ~blk[wl * WIN + lr];
                        alive &= ~(1ull << j);
                    }
                    s_nk = nk; s_kept = kept; s_nkc = nkc;
                    if (kept >= TOPN) s_done = 1;
                }
                __syncthreads();
                if (s_done) break;
                int nk = s_nk;
                if (nk > 0 && t < WRD - 1 - wl) {
                    int w2 = wl + 1 + t;
                    u64 acc = rem[w2];
                    int q0 = s_nkc - nk;
                    for (int q = q0; q < s_nkc; q++) acc |= blk[w2 * WIN + ckeptL[q]];
                    rem[w2] = acc;
                }
                __syncthreads();
            }

            // publish kept boxes + counts
            int nkc = s_nkc;
            int kept0 = s_k0;
            for (int q = t; q < nkc; q += 512) {
                int c = k * WIN + ckeptL[q];
                g_kbox[b][kept0 + q]  = g_sbox[b][c];
                g_karea[b][kept0 + q] = g_sarea[b][c];
            }
            if (t == 0) {
                s_dlo = kept0; s_dhi = s_kept;
                g_kc[b][(k + 1) & 1] = s_kept;
                g_keptCnt[b] = s_kept;
                if (s_done) g_done[b] = 1;
            }
        } else if (r >= 1 && r <= 32 && kn < NWIN) {
            // kept(through k-1) vs window k+1
            int keptPrev = g_kc[b][k & 1];
            if ((r - 1) * 64 < keptPrev) {
                if (t < WRD) red[t] = 0;
                for (int j = t; j < WIN; j += 512) {
                    cbx[j] = g_sbox[b][kn * WIN + j];
                    car[j] = g_sarea[b][kn * WIN + j];
                }
                __syncthreads();
                int kr = (r - 1) * 64 + rl;
                if (kr < keptPrev) {
                    float4 bi = g_kbox[b][kr];
                    float  ai = g_karea[b][kr];
#pragma unroll
                    for (int ww = 0; ww < 2; ww++) {
                        int w = cg * 2 + ww;
                        u64 v = iou_word(bi, ai, cbx, car, w * 64);
                        if (v) atomicOr(&red[w], v);
                    }
                }
                __syncthreads();
                if (t < WRD && red[t]) atomicOr((u64*)&g_remwAll[b][kn][t], red[t]);
            }
        } else if (r >= 33 && r < 49 && kn < NWIN && kn >= PROWIN) {
            // on-demand in-window mask of window k+1
            for (int j = t; j < WIN; j += 512) {
                cbx[j] = g_sbox[b][kn * WIN + j];
                car[j] = g_sarea[b][kn * WIN + j];
            }
            __syncthreads();
            int rb = r - 33;
            int i  = kn * WIN + rb * 64 + rl;
            float4 bi = g_sbox[b][i];
            float  ai = g_sarea[b][i];
#pragma unroll
            for (int ww = 0; ww < 2; ww++) {
                int w = cg * 2 + ww;
                u64 v = iou_word(bi, ai, cbx, car, w * 64);
                if (w == rb) v &= (rl == 63) ? 0ull : (~0ull << (rl + 1));
                g_awmask[b][kn][w][rb * 64 + rl] = v;
            }
        }

        bbar(b, gen++);
        if (*(volatile int*)&g_done[b]) break;
    }
}

// ----------------------------------------------------------------- out ----
__global__ __launch_bounds__(256) void k_out(float* __restrict__ out)
{
    int idx = blockIdx.x * 256 + threadIdx.x;
    if (idx >= NB * TOPN) return;
    int b = idx / TOPN;
    int r = idx - b * TOPN;
    float* o = out + (size_t)idx * 5;
    if (r < g_keptCnt[b]) {
        int c = g_keptIdx[b][r];
        float4 bx = g_sbox[b][c];
        o[0] = g_sscore[b][c];
        o[1] = bx.x; o[2] = bx.y; o[3] = bx.z; o[4] = bx.w;
    } else {
        o[0] = 0.f; o[1] = 0.f; o[2] = 0.f; o[3] = 0.f; o[4] = 0.f;
    }
}

extern "C" void kernel_launch(void* const* d_in, const int* in_sizes, int n_in,
                              void* d_out, int out_size)
{
    const float* sm  = (const float*)d_in[0];
    const float* bd  = (const float*)d_in[1];
    const float* img = (const float*)d_in[2];
    float* out = (float*)d_out;

    cudaFuncSetAttribute(k_sort_local,
                         cudaFuncAttributeMaxDynamicSharedMemorySize, 65536);
    cudaFuncSetAttribute(k_nms,
                         cudaFuncAttributeMaxDynamicSharedMemorySize, 151552);

    k_prep<<<dim3(NPAD / 256, NB), 256>>>(sm, bd, img);

    const int nchunks = NB * NPAD / 8192;          // 16
    k_sort_local<<<nchunks, 1024, 65536>>>(0);
    k_sort_global<<<NB * NPAD / 256, 256>>>(16384, 8192);
    k_sort_local<<<nchunks, 1024, 65536>>>(16384);
    k_sort_global<<<NB * NPAD / 256, 256>>>(32768, 16384);
    k_sort_global<<<NB * NPAD / 256, 256>>>(32768, 8192);
    k_sort_local<<<nchunks, 1024, 65536>>>(32768);
    k_sort_global<<<NB * NPAD / 256, 256>>>(65536, 32768);
    k_sort_global<<<NB * NPAD / 256, 256>>>(65536, 16384);
    k_sort_global<<<NB * NPAD / 256, 256>>>(65536, 8192);
    k_sort_local<<<nchunks, 1024, 65536>>>(65536);

    k_gather<<<dim3(NPROP / 256, NB), 256>>>();

    k_nms<<<dim3(BLKB, NB), 512, 151552>>>();

    k_out<<<(NB * TOPN + 255) / 256, 256>>>(out);
}

// round 9
// speedup vs baseline: 1.0407x; 1.0407x over previous
#include <cuda_runtime.h>
#include <cstdint>

#define NB    2
#define NA    9
#define NHW   4096        // 64*64
#define NPROP 36864       // NHW*NA
#define NPAD  65536
#define TOPN  2000
#define WIN   1024        // candidates per window
#define WRD   16          // 64-bit words per window
#define NWIN  36          // WIN*NWIN = NPROP
#define BLKB  25          // persistent blocks per batch: 1 + 8 + 16

typedef unsigned long long u64;

// Anchors from generate_anchors(16,(0.5,1,2),(8,16,32)) with base [0,0,15,15].
__constant__ float c_anchors[9][4] = {
  { -84.f,  -40.f,  99.f,  55.f},
  {-176.f,  -88.f, 191.f, 103.f},
  {-360.f, -184.f, 375.f, 199.f},
  { -56.f,  -56.f,  71.f,  71.f},
  {-120.f, -120.f, 135.f, 135.f},
  {-248.f, -248.f, 263.f, 263.f},
  { -36.f,  -80.f,  51.f,  95.f},
  { -80.f, -168.f,  95.f, 183.f},
  {-168.f, -344.f, 183.f, 359.f}
};

__device__ float4 g_boxes [NB][NPROP];
__device__ float  g_scores[NB][NPROP];
__device__ u64    g_keys  [NB * NPAD];
__device__ float4 g_sbox  [NB][NPROP];
__device__ float  g_sscore[NB][NPROP];
__device__ float  g_sarea [NB][NPROP];
__device__ u64    g_awmask[NB][NWIN][WRD][WIN]; // in-window masks (on demand)
__device__ u64    g_remwAll[NB][NWIN][WRD];     // per-window kept suppression
__device__ float4 g_kbox  [NB][TOPN];
__device__ float  g_karea [NB][TOPN];
__device__ int    g_keptIdx[NB][TOPN];
__device__ int    g_keptCnt[NB];
__device__ int    g_kc[NB][2];                  // ping-pong published count
__device__ int    g_done  [NB];
__device__ unsigned g_barcnt[NB];
__device__ unsigned g_bargen[NB];

// per-batch software barrier across BLKB co-resident blocks
// (atomic arrive; waiters poll a volatile load WITH nanosleep backoff)
__device__ __forceinline__ void bbar(int b, int gen)
{
    __syncthreads();
    if (threadIdx.x == 0) {
        __threadfence();
        unsigned arrive = atomicAdd(&g_barcnt[b], 1u) + 1u;
        if (arrive == (unsigned)BLKB * (unsigned)gen) {
            atomicExch(&g_bargen[b], (unsigned)gen);
        } else {
            while (*(volatile unsigned*)&g_bargen[b] < (unsigned)gen)
                __nanosleep(64);
        }
        __threadfence();
    }
    __syncthreads();
}

// IoU>0.7 bits of box (bi,ai) vs 64 smem boxes starting at wb.
// Branch-free band + exact __fdiv_rn resolution (reference op order).
__device__ __forceinline__ u64 iou_word(float4 bi, float ai,
                                        const float4* cbx, const float* car,
                                        int wb)
{
    u64 bsup = 0, bamb = 0;
#pragma unroll 8
    for (int j2 = 0; j2 < 64; j2++) {
        float4 bj = cbx[wb + j2];
        float  aj = car[wb + j2];
        float iw = fmaxf(__fadd_rn(__fsub_rn(fminf(bi.z, bj.z), fmaxf(bi.x, bj.x)), 1.0f), 0.0f);
        float ih = fmaxf(__fadd_rn(__fsub_rn(fminf(bi.w, bj.w), fmaxf(bi.y, bj.y)), 1.0f), 0.0f);
        float inter = __fmul_rn(iw, ih);
        float s     = __fadd_rn(ai, aj);
        bool hi = inter > __fmul_rn(s, 0.411775f);
        bool lo = inter < __fmul_rn(s, 0.411755f);
        bsup |= ((u64)hi) << j2;
        bamb |= ((u64)(!hi && !lo)) << j2;
    }
    while (bamb) {
        int j2 = __ffsll((long long)bamb) - 1;
        bamb &= bamb - 1;
        float4 bj = cbx[wb + j2];
        float iw = fmaxf(__fadd_rn(__fsub_rn(fminf(bi.z, bj.z), fmaxf(bi.x, bj.x)), 1.0f), 0.0f);
        float ih = fmaxf(__fadd_rn(__fsub_rn(fminf(bi.w, bj.w), fmaxf(bi.y, bj.y)), 1.0f), 0.0f);
        float inter = __fmul_rn(iw, ih);
        float s     = __fadd_rn(ai, car[wb + j2]);
        float denom = __fsub_rn(s, inter);
        if (__fdiv_rn(inter, denom) > 0.7f) bsup |= (1ull << j2);
    }
    return bsup;
}

// ---------------------------------------------------------------- prep ----
__global__ __launch_bounds__(256) void k_prep(const float* __restrict__ sm,
                                              const float* __restrict__ bd,
                                              const float* __restrict__ img)
{
    int b = blockIdx.y;
    int i = blockIdx.x * 256 + threadIdx.x;       // 0..NPAD-1
    if (i == 0) {
        g_done[b] = 0; g_keptCnt[b] = 0;
        g_kc[b][0] = 0; g_kc[b][1] = 0;
        g_barcnt[b] = 0; g_bargen[b] = 0;
    }
    if (i < NWIN * WRD) g_remwAll[b][i >> 4][i & 15] = 0;
    if (i >= NPAD) return;
    if (i >= NPROP) { g_keys[b * NPAD + i] = ~0ull; return; }

    int a  = i % NA;
    int hw = i / NA;
    float cx = (float)((hw & 63) * 16 + 8);
    float cy = (float)((hw >> 6) * 16 + 8);

    float ax1 = cx + c_anchors[a][0];
    float ay1 = cy + c_anchors[a][1];
    float ax2 = cx + c_anchors[a][2];
    float ay2 = cy + c_anchors[a][3];

    float wA = ax2 - ax1 + 1.0f;                  // exact small integers
    float hA = ay2 - ay1 + 1.0f;
    float ctrx = __fadd_rn(ax1, __fmul_rn(0.5f, wA));
    float ctry = __fadd_rn(ay1, __fmul_rn(0.5f, hA));

    const float* bdb = bd + ((size_t)b * 36 + (size_t)a * 4) * NHW + hw;
    float dx = bdb[0];
    float dy = bdb[NHW];
    float dw = bdb[2 * NHW];
    float dh = bdb[3 * NHW];

    // reference op order: mul then add, no contraction
    float pcx = __fadd_rn(__fmul_rn(dx, wA), ctrx);
    float pcy = __fadd_rn(__fmul_rn(dy, hA), ctry);
    float pw  = __fmul_rn(expf(dw), wA);
    float ph  = __fmul_rn(expf(dh), hA);

    float x1 = __fsub_rn(pcx, __fmul_rn(0.5f, pw));
    float y1 = __fsub_rn(pcy, __fmul_rn(0.5f, ph));
    float x2 = __fadd_rn(pcx, __fmul_rn(0.5f, pw));
    float y2 = __fadd_rn(pcy, __fmul_rn(0.5f, ph));

    float imh = img[b * 3 + 0];
    float imw = img[b * 3 + 1];
    float mx  = __fsub_rn(imw, 1.0f);
    float my  = __fsub_rn(imh, 1.0f);
    x1 = fminf(fmaxf(x1, 0.0f), mx);
    x2 = fminf(fmaxf(x2, 0.0f), mx);
    y1 = fminf(fmaxf(y1, 0.0f), my);
    y2 = fminf(fmaxf(y2, 0.0f), my);

    float s = sm[((size_t)b * 18 + 9 + a) * NHW + hw];

    g_boxes[b][i]  = make_float4(x1, y1, x2, y2);
    g_scores[b][i] = s;

    unsigned u = __float_as_uint(s);
    unsigned k = (u & 0x80000000u) ? ~u : (u | 0x80000000u);  // ascending
    unsigned kd = ~k;                                          // descending
    g_keys[b * NPAD + i] = ((u64)kd << 32) | (unsigned)i;
}

// ---------------------------------------------------------------- sort ----
// 8192-element chunks in 64KB dynamic smem (16 blocks). Canonical bitonic:
// ascending iff ((li & len) == 0).
__global__ __launch_bounds__(1024) void k_sort_local(int startLen)
{
    extern __shared__ u64 sk[];
    int base = blockIdx.x * 8192;                 // flat over NB*NPAD
    int tid  = threadIdx.x;

#pragma unroll
    for (int e = 0; e < 8; e++) sk[e * 1024 + tid] = g_keys[base + e * 1024 + tid];
    __syncthreads();

    if (startLen == 0) {
        for (int len = 2; len <= 8192; len <<= 1) {
            for (int d = len >> 1; d > 0; d >>= 1) {
#pragma unroll
                for (int e = 0; e < 4; e++) {
                    int idx = e * 1024 + tid;          // 0..4095 pair ids
                    int i = ((idx & ~(d - 1)) << 1) | (idx & (d - 1));
                    int j = i | d;
                    int li = (base + i) & (NPAD - 1);
                    bool asc = ((li & len) == 0);
                    u64 a = sk[i], c = sk[j];
                    if ((a > c) == asc) { sk[i] = c; sk[j] = a; }
                }
                __syncthreads();
            }
        }
    } else {
        bool asc = (((base & (NPAD - 1)) & startLen) == 0);
        for (int d = 4096; d > 0; d >>= 1) {
#pragma unroll
            for (int e = 0; e < 4; e++) {
                int idx = e * 1024 + tid;
                int i = ((idx & ~(d - 1)) << 1) | (idx & (d - 1));
                int j = i | d;
                u64 a = sk[i], c = sk[j];
                if ((a > c) == asc) { sk[i] = c; sk[j] = a; }
            }
            __syncthreads();
        }
    }

#pragma unroll
    for (int e = 0; e < 8; e++) g_keys[base + e * 1024 + tid] = sk[e * 1024 + tid];
}

__global__ __launch_bounds__(256) void k_sort_global(int len, int d)
{
    int i = blockIdx.x * 256 + threadIdx.x;       // flat element index
    if (i >= NB * NPAD) return;
    int li = i & (NPAD - 1);
    if (li & d) return;
    int j = i + d;                                 // same batch since (li&d)==0
    bool asc = ((li & len) == 0);
    u64 a = g_keys[i], c = g_keys[j];
    if ((a > c) == asc) { g_keys[i] = c; g_keys[j] = a; }
}

// -------------------------------------------------------------- gather ----
__global__ __launch_bounds__(256) void k_gather()
{
    int b = blockIdx.y;
    int p = blockIdx.x * 256 + threadIdx.x;
    if (p >= NPROP) return;
    unsigned idx = (unsigned)(g_keys[b * NPAD + p] & 0xFFFFFFFFull);
    float4 bx = g_boxes[b][idx];
    g_sbox[b][p]   = bx;
    g_sscore[b][p] = g_scores[b][idx];
    g_sarea[b][p]  = __fmul_rn(__fadd_rn(__fsub_rn(bx.z, bx.x), 1.0f),
                               __fadd_rn(__fsub_rn(bx.w, bx.y), 1.0f));
}

// ------------------------------------------------- persistent NMS loop ----
// grid (BLKB, NB), 512 threads, 148KB dyn smem (1 block/SM, co-resident).
// Pre-loop: blocks 9..24 mask window 0. Iteration k (ONE barrier at end):
//   r==0:    rem = g_remwAll[k] | (keeps of window k-1 vs window k);
//            resolve window k entirely in smem; publish keeps.
//   r 1..8:  kept(through k-1) vs window k+1 -> g_remwAll[k+1] (64 rows/pass).
//   r 9..24: in-window mask of window k+1 (one 64-row block each).
__global__ __launch_bounds__(512) void k_nms()
{
    int b = blockIdx.y;
    int r = blockIdx.x;                // 0..BLKB-1
    int t = threadIdx.x;
    int rl = t & 63;
    int cg = t >> 6;                   // 0..7, two words each

    extern __shared__ char dynsmem[];
    u64*    blk = (u64*)dynsmem;                       // 128KB (resolve)
    float4* cbx = (float4*)(dynsmem + 131072);         // 16KB
    float*  car = (float*)(dynsmem + 131072 + 16384);  // 4KB

    __shared__ u64 red[WRD];
    __shared__ u64 rem[WRD];
    __shared__ short ckeptL[WIN];
    __shared__ int s_kept, s_nk, s_nkc, s_done, s_dlo, s_dhi, s_k0;

    if (t == 0) { s_kept = 0; s_dlo = 0; s_dhi = 0; }

    // ---- pre-loop: in-window mask of window 0 (blocks 9..24) ----
    if (r >= 9 && r < 25) {
        for (int j = t; j < WIN; j += 512) {
            cbx[j] = g_sbox[b][j];
            car[j] = g_sarea[b][j];
        }
        __syncthreads();
        int rb = r - 9;
        int i  = rb * 64 + rl;
        float4 bi = g_sbox[b][i];
        float  ai = g_sarea[b][i];
#pragma unroll
        for (int ww = 0; ww < 2; ww++) {
            int w = cg * 2 + ww;
            u64 v = iou_word(bi, ai, cbx, car, w * 64);
            if (w == rb) v &= (rl == 63) ? 0ull : (~0ull << (rl + 1));
            g_awmask[b][0][w][rb * 64 + rl] = v;
        }
    }

    int gen = 1;
    bbar(b, gen++);

    // ---- pipelined window loop ----
    for (int k = 0; k < NWIN; k++) {
        int kn = k + 1;
        if (r == 0) {
            // load window k columns + mask + base suppression
            for (int j = t; j < WIN; j += 512) {
                cbx[j] = g_sbox[b][k * WIN + j];
                car[j] = g_sarea[b][k * WIN + j];
            }
            const ulonglong2* src = (const ulonglong2*)&g_awmask[b][k][0][0];
            ulonglong2* dst = (ulonglong2*)blk;
#pragma unroll
            for (int q = 0; q < WRD; q++) dst[q * 512 + t] = src[q * 512 + t];
            if (t < WRD) rem[t] = g_remwAll[b][k][t];
            if (t == 0) { s_k0 = s_kept; s_done = 0; s_nkc = 0; }
            __syncthreads();

            // delta: keeps found in window k-1 vs window k
            for (int q = s_dlo + (t >> 4); q < s_dhi; q += 32) {
                float4 bi = g_kbox[b][q];
                float  ai = g_karea[b][q];
                u64 v = iou_word(bi, ai, cbx, car, (t & 15) * 64);
                if (v) atomicOr(&rem[t & 15], v);
            }
            __syncthreads();

            // resolve window k in smem
            for (int wl = 0; wl < WRD; wl++) {
                if (t == 0) {
                    u64 alive = ~rem[wl];
                    int nk = 0, kept = s_kept, nkc = s_nkc;
                    while (alive && kept < TOPN) {
                        int j = __ffsll((long long)alive) - 1;
                        int lr = wl * 64 + j;
                        g_keptIdx[b][kept++] = k * WIN + lr;
                        ckeptL[nkc++] = (short)lr;
                        nk++;
                        alive &= ~blk[wl * WIN + lr];
                        alive &= ~(1ull << j);
                    }
                    s_nk = nk; s_kept = kept; s_nkc = nkc;
                    if (kept >= TOPN) s_done = 1;
                }
                __syncthreads();
                if (s_done) break;
                int nk = s_nk;
                if (nk > 0 && t < WRD - 1 - wl) {
                    int w2 = wl + 1 + t;
                    u64 acc = rem[w2];
                    int q0 = s_nkc - nk;
                    for (int q = q0; q < s_nkc; q++) acc |= blk[w2 * WIN + ckeptL[q]];
                    rem[w2] = acc;
                }
                __syncthreads();
            }

            // publish kept boxes + counts
            int nkc = s_nkc;
            int kept0 = s_k0;
            for (int q = t; q < nkc; q += 512) {
                int c = k * WIN + ckeptL[q];
                g_kbox[b][kept0 + q]  = g_sbox[b][c];
                g_karea[b][kept0 + q] = g_sarea[b][c];
            }
            if (t == 0) {
                s_dlo = kept0; s_dhi = s_kept;
                g_kc[b][(k + 1) & 1] = s_kept;
                g_keptCnt[b] = s_kept;
                if (s_done) g_done[b] = 1;
            }
        } else if (r >= 1 && r <= 8 && kn < NWIN) {
            // kept(through k-1) vs window k+1 (64 rows per block per pass)
            int keptPrev = g_kc[b][k & 1];
            if ((r - 1) * 64 < keptPrev) {
                if (t < WRD) red[t] = 0;
                for (int j = t; j < WIN; j += 512) {
                    cbx[j] = g_sbox[b][kn * WIN + j];
                    car[j] = g_sarea[b][kn * WIN + j];
                }
                __syncthreads();
                for (int kr0 = (r - 1) * 64; kr0 < keptPrev; kr0 += 8 * 64) {
                    int kr = kr0 + rl;
                    if (kr < keptPrev) {
                        float4 bi = g_kbox[b][kr];
                        float  ai = g_karea[b][kr];
#pragma unroll
                        for (int ww = 0; ww < 2; ww++) {
                            int w = cg * 2 + ww;
                            u64 v = iou_word(bi, ai, cbx, car, w * 64);
                            if (v) atomicOr(&red[w], v);
                        }
                    }
                }
                __syncthreads();
                if (t < WRD && red[t]) atomicOr((u64*)&g_remwAll[b][kn][t], red[t]);
            }
        } else if (r >= 9 && r < 25 && kn < NWIN) {
            // in-window mask of window k+1
            for (int j = t; j < WIN; j += 512) {
                cbx[j] = g_sbox[b][kn * WIN + j];
                car[j] = g_sarea[b][kn * WIN + j];
            }
            __syncthreads();
            int rb = r - 9;
            int i  = kn * WIN + rb * 64 + rl;
            float4 bi = g_sbox[b][i];
            float  ai = g_sarea[b][i];
#pragma unroll
            for (int ww = 0; ww < 2; ww++) {
                int w = cg * 2 + ww;
                u64 v = iou_word(bi, ai, cbx, car, w * 64);
                if (w == rb) v &= (rl == 63) ? 0ull : (~0ull << (rl + 1));
                g_awmask[b][kn][w][rb * 64 + rl] = v;
            }
        }

        bbar(b, gen++);
        if (*(volatile int*)&g_done[b]) break;
    }
}

// ----------------------------------------------------------------- out ----
__global__ __launch_bounds__(256) void k_out(float* __restrict__ out)
{
    int idx = blockIdx.x * 256 + threadIdx.x;
    if (idx >= NB * TOPN) return;
    int b = idx / TOPN;
    int r = idx - b * TOPN;
    float* o = out + (size_t)idx * 5;
    if (r < g_keptCnt[b]) {
        int c = g_keptIdx[b][r];
        float4 bx = g_sbox[b][c];
        o[0] = g_sscore[b][c];
        o[1] = bx.x; o[2] = bx.y; o[3] = bx.z; o[4] = bx.w;
    } else {
        o[0] = 0.f; o[1] = 0.f; o[2] = 0.f; o[3] = 0.f; o[4] = 0.f;
    }
}

extern "C" void kernel_launch(void* const* d_in, const int* in_sizes, int n_in,
                              void* d_out, int out_size)
{
    const float* sm  = (const float*)d_in[0];
    const float* bd  = (const float*)d_in[1];
    const float* img = (const float*)d_in[2];
    float* out = (float*)d_out;

    cudaFuncSetAttribute(k_sort_local,
                         cudaFuncAttributeMaxDynamicSharedMemorySize, 65536);
    cudaFuncSetAttribute(k_nms,
                         cudaFuncAttributeMaxDynamicSharedMemorySize, 151552);

    k_prep<<<dim3(NPAD / 256, NB), 256>>>(sm, bd, img);

    const int nchunks = NB * NPAD / 8192;          // 16
    k_sort_local<<<nchunks, 1024, 65536>>>(0);
    k_sort_global<<<NB * NPAD / 256, 256>>>(16384, 8192);
    k_sort_local<<<nchunks, 1024, 65536>>>(16384);
    k_sort_global<<<NB * NPAD / 256, 256>>>(32768, 16384);
    k_sort_global<<<NB * NPAD / 256, 256>>>(32768, 8192);
    k_sort_local<<<nchunks, 1024, 65536>>>(32768);
    k_sort_global<<<NB * NPAD / 256, 256>>>(65536, 32768);
    k_sort_global<<<NB * NPAD / 256, 256>>>(65536, 16384);
    k_sort_global<<<NB * NPAD / 256, 256>>>(65536, 8192);
    k_sort_local<<<nchunks, 1024, 65536>>>(65536);

    k_gather<<<dim3(NPROP / 256, NB), 256>>>();

    k_nms<<<dim3(BLKB, NB), 512, 151552>>>();

    k_out<<<(NB * TOPN + 255) / 256, 256>>>(out);
}

// round 11
// speedup vs baseline: 1.3237x; 1.2719x over previous
#include <cuda_runtime.h>
#include <cstdint>

#define NB    2
#define NA    9
#define NHW   4096        // 64*64
#define NPROP 36864       // NHW*NA
#define NPAD  65536
#define TOPN  2000
#define WIN   1024        // candidates per window
#define WRD   16          // 64-bit words per window
#define NWIN  36          // WIN*NWIN = NPROP
#define NPAIR 18          // windows processed two at a time

typedef unsigned long long u64;

// Anchors from generate_anchors(16,(0.5,1,2),(8,16,32)) with base [0,0,15,15].
__constant__ float c_anchors[9][4] = {
  { -84.f,  -40.f,  99.f,  55.f},
  {-176.f,  -88.f, 191.f, 103.f},
  {-360.f, -184.f, 375.f, 199.f},
  { -56.f,  -56.f,  71.f,  71.f},
  {-120.f, -120.f, 135.f, 135.f},
  {-248.f, -248.f, 263.f, 263.f},
  { -36.f,  -80.f,  51.f,  95.f},
  { -80.f, -168.f,  95.f, 183.f},
  {-168.f, -344.f, 183.f, 359.f}
};

__device__ float4 g_boxes [NB][NPROP];
__device__ float  g_scores[NB][NPROP];
__device__ u64    g_keys  [NB * NPAD];
__device__ float4 g_sbox  [NB][NPROP];
__device__ float  g_sscore[NB][NPROP];
__device__ float  g_sarea [NB][NPROP];
__device__ u64    g_wmaskP[NB][2][WRD][WIN]; // pair of window masks
__device__ u64    g_remwP [NB][2][WRD];      // kept suppression per window
__device__ float4 g_kbox  [NB][TOPN];
__device__ float  g_karea [NB][TOPN];
__device__ int    g_keptIdx[NB][TOPN];
__device__ int    g_keptCnt[NB];
__device__ int    g_done  [NB];

// IoU>0.7 bits of box (bi,ai) vs 64 smem boxes starting at wb.
// Branch-free band + exact __fdiv_rn resolution (reference op order).
__device__ __forceinline__ u64 iou_word(float4 bi, float ai,
                                        const float4* cbx, const float* car,
                                        int wb)
{
    u64 bsup = 0, bamb = 0;
#pragma unroll 8
    for (int j2 = 0; j2 < 64; j2++) {
        float4 bj = cbx[wb + j2];
        float  aj = car[wb + j2];
        float iw = fmaxf(__fadd_rn(__fsub_rn(fminf(bi.z, bj.z), fmaxf(bi.x, bj.x)), 1.0f), 0.0f);
        float ih = fmaxf(__fadd_rn(__fsub_rn(fminf(bi.w, bj.w), fmaxf(bi.y, bj.y)), 1.0f), 0.0f);
        float inter = __fmul_rn(iw, ih);
        float s     = __fadd_rn(ai, aj);
        bool hi = inter > __fmul_rn(s, 0.411775f);
        bool lo = inter < __fmul_rn(s, 0.411755f);
        bsup |= ((u64)hi) << j2;
        bamb |= ((u64)(!hi && !lo)) << j2;
    }
    while (bamb) {
        int j2 = __ffsll((long long)bamb) - 1;
        bamb &= bamb - 1;
        float4 bj = cbx[wb + j2];
        float iw = fmaxf(__fadd_rn(__fsub_rn(fminf(bi.z, bj.z), fmaxf(bi.x, bj.x)), 1.0f), 0.0f);
        float ih = fmaxf(__fadd_rn(__fsub_rn(fminf(bi.w, bj.w), fmaxf(bi.y, bj.y)), 1.0f), 0.0f);
        float inter = __fmul_rn(iw, ih);
        float s     = __fadd_rn(ai, car[wb + j2]);
        float denom = __fsub_rn(s, inter);
        if (__fdiv_rn(inter, denom) > 0.7f) bsup |= (1ull << j2);
    }
    return bsup;
}

// ---------------------------------------------------------------- prep ----
__global__ __launch_bounds__(256) void k_prep(const float* __restrict__ sm,
                                              const float* __restrict__ bd,
                                              const float* __restrict__ img)
{
    int b = blockIdx.y;
    int i = blockIdx.x * 256 + threadIdx.x;       // 0..NPAD-1
    if (i == 0) { g_done[b] = 0; g_keptCnt[b] = 0; }
    if (i < 2 * WRD) g_remwP[b][i >> 4][i & 15] = 0;
    if (i >= NPAD) return;
    if (i >= NPROP) { g_keys[b * NPAD + i] = ~0ull; return; }

    int a  = i % NA;
    int hw = i / NA;
    float cx = (float)((hw & 63) * 16 + 8);
    float cy = (float)((hw >> 6) * 16 + 8);

    float ax1 = cx + c_anchors[a][0];
    float ay1 = cy + c_anchors[a][1];
    float ax2 = cx + c_anchors[a][2];
    float ay2 = cy + c_anchors[a][3];

    float wA = ax2 - ax1 + 1.0f;                  // exact small integers
    float hA = ay2 - ay1 + 1.0f;
    float ctrx = __fadd_rn(ax1, __fmul_rn(0.5f, wA));
    float ctry = __fadd_rn(ay1, __fmul_rn(0.5f, hA));

    const float* bdb = bd + ((size_t)b * 36 + (size_t)a * 4) * NHW + hw;
    float dx = bdb[0];
    float dy = bdb[NHW];
    float dw = bdb[2 * NHW];
    float dh = bdb[3 * NHW];

    // reference op order: mul then add, no contraction
    float pcx = __fadd_rn(__fmul_rn(dx, wA), ctrx);
    float pcy = __fadd_rn(__fmul_rn(dy, hA), ctry);
    float pw  = __fmul_rn(expf(dw), wA);
    float ph  = __fmul_rn(expf(dh), hA);

    float x1 = __fsub_rn(pcx, __fmul_rn(0.5f, pw));
    float y1 = __fsub_rn(pcy, __fmul_rn(0.5f, ph));
    float x2 = __fadd_rn(pcx, __fmul_rn(0.5f, pw));
    float y2 = __fadd_rn(pcy, __fmul_rn(0.5f, ph));

    float imh = img[b * 3 + 0];
    float imw = img[b * 3 + 1];
    float mx  = __fsub_rn(imw, 1.0f);
    float my  = __fsub_rn(imh, 1.0f);
    x1 = fminf(fmaxf(x1, 0.0f), mx);
    x2 = fminf(fmaxf(x2, 0.0f), mx);
    y1 = fminf(fmaxf(y1, 0.0f), my);
    y2 = fminf(fmaxf(y2, 0.0f), my);

    float s = sm[((size_t)b * 18 + 9 + a) * NHW + hw];

    g_boxes[b][i]  = make_float4(x1, y1, x2, y2);
    g_scores[b][i] = s;

    unsigned u = __float_as_uint(s);
    unsigned k = (u & 0x80000000u) ? ~u : (u | 0x80000000u);  // ascending
    unsigned kd = ~k;                                          // descending
    g_keys[b * NPAD + i] = ((u64)kd << 32) | (unsigned)i;
}

// ---------------------------------------------------------------- sort ----
// 16384-element chunks in 128KB dynamic smem. Canonical bitonic:
// ascending iff ((li & len) == 0).
__global__ __launch_bounds__(1024) void k_sort_local(int startLen)
{
    extern __shared__ u64 sk[];
    int base = blockIdx.x * 16384;                // flat over NB*NPAD
    int tid  = threadIdx.x;

#pragma unroll
    for (int e = 0; e < 16; e++) sk[e * 1024 + tid] = g_keys[base + e * 1024 + tid];
    __syncthreads();

    if (startLen == 0) {
        for (int len = 2; len <= 16384; len <<= 1) {
            for (int d = len >> 1; d > 0; d >>= 1) {
#pragma unroll
                for (int e = 0; e < 8; e++) {
                    int idx = e * 1024 + tid;          // 0..8191 pair ids
                    int i = ((idx & ~(d - 1)) << 1) | (idx & (d - 1));
                    int j = i | d;
                    int li = (base + i) & (NPAD - 1);
                    bool asc = ((li & len) == 0);
                    u64 a = sk[i], c = sk[j];
                    if ((a > c) == asc) { sk[i] = c; sk[j] = a; }
                }
                __syncthreads();
            }
        }
    } else {
        bool asc = (((base & (NPAD - 1)) & startLen) == 0);
        for (int d = 8192; d > 0; d >>= 1) {
#pragma unroll
            for (int e = 0; e < 8; e++) {
                int idx = e * 1024 + tid;
                int i = ((idx & ~(d - 1)) << 1) | (idx & (d - 1));
                int j = i | d;
                u64 a = sk[i], c = sk[j];
                if ((a > c) == asc) { sk[i] = c; sk[j] = a; }
            }
            __syncthreads();
        }
    }

#pragma unroll
    for (int e = 0; e < 16; e++) g_keys[base + e * 1024 + tid] = sk[e * 1024 + tid];
}

__global__ __launch_bounds__(256) void k_sort_global(int len, int d)
{
    int i = blockIdx.x * 256 + threadIdx.x;       // flat element index
    if (i >= NB * NPAD) return;
    int li = i & (NPAD - 1);
    if (li & d) return;
    int j = i + d;                                 // same batch since (li&d)==0
    bool asc = ((li & len) == 0);
    u64 a = g_keys[i], c = g_keys[j];
    if ((a > c) == asc) { g_keys[i] = c; g_keys[j] = a; }
}

// -------------------------------------------------------------- gather ----
__global__ __launch_bounds__(256) void k_gather()
{
    int b = blockIdx.y;
    int p = blockIdx.x * 256 + threadIdx.x;
    if (p >= NPROP) return;
    unsigned idx = (unsigned)(g_keys[b * NPAD + p] & 0xFFFFFFFFull);
    float4 bx = g_boxes[b][idx];
    g_sbox[b][p]   = bx;
    g_sscore[b][p] = g_scores[b][idx];
    g_sarea[b][p]  = __fmul_rn(__fadd_rn(__fsub_rn(bx.z, bx.x), 1.0f),
                               __fadd_rn(__fsub_rn(bx.w, bx.y), 1.0f));
}

// ----------------------------------------------------- pair mask kernel ----
// Pair p = windows (2p, 2p+1). 64 blocks per batch:
//   0..15 : in-window mask of window 2p   (row-group bx)
//   16..31: in-window mask of window 2p+1 (row-group bx-16)
//   32..47: kept(through 2p-1) vs window 2p   -> g_remwP[b][0]
//   48..63: kept(through 2p-1) vs window 2p+1 -> g_remwP[b][1]
__global__ __launch_bounds__(512) void k_maskw(int p)
{
    int b = blockIdx.y;
    if (g_done[b]) return;
    int bx = blockIdx.x;
    int t  = threadIdx.x;
    int rl = t & 63;
    int cg = t >> 6;                   // 0..7, two words each

    __shared__ float4 cbx[WIN];
    __shared__ float  car[WIN];
    __shared__ u64    red[WRD];

    if (bx < 32) {
        int win = 2 * p + (bx >> 4);
        int rb  = bx & 15;
        int W0  = win * WIN;
        for (int j = t; j < WIN; j += 512) {
            cbx[j] = g_sbox[b][W0 + j];
            car[j] = g_sarea[b][W0 + j];
        }
        __syncthreads();
        int i = W0 + rb * 64 + rl;
        float4 bi = g_sbox[b][i];
        float  ai = g_sarea[b][i];
#pragma unroll
        for (int ww = 0; ww < 2; ww++) {
            int w = cg * 2 + ww;
            u64 v = iou_word(bi, ai, cbx, car, w * 64);
            if (w == rb) v &= (rl == 63) ? 0ull : (~0ull << (rl + 1));
            g_wmaskP[b][win & 1][w][rb * 64 + rl] = v;
        }
    } else {
        int win = 2 * p + ((bx - 32) >> 4);
        int kb  = (bx - 32) & 15;
        int keptCnt = g_keptCnt[b];
        if (kb * 64 >= keptCnt) return;
        int W0 = win * WIN;
        if (t < WRD) red[t] = 0;
        for (int j = t; j < WIN; j += 512) {
            cbx[j] = g_sbox[b][W0 + j];
            car[j] = g_sarea[b][W0 + j];
        }
        __syncthreads();
        for (int kr0 = kb * 64; kr0 < keptCnt; kr0 += 16 * 64) {
            int kr = kr0 + rl;
            if (kr < keptCnt) {
                float4 bi = g_kbox[b][kr];
                float  ai = g_karea[b][kr];
#pragma unroll
                for (int ww = 0; ww < 2; ww++) {
                    int w = cg * 2 + ww;
                    u64 v = iou_word(bi, ai, cbx, car, w * 64);
                    if (v) atomicOr(&red[w], v);
                }
            }
        }
        __syncthreads();
        if (t < WRD && red[t]) atomicOr((u64*)&g_remwP[b][win & 1][t], red[t]);
    }
}

// ----------------------------------------------------- pair scan kernel ----
// One block per batch. Resolve window 2p from smem; apply new keeps of 2p to
// window 2p+1's suppression internally; resolve 2p+1. Publish keeps once.
// ckeptL sized 2*WIN: a pair can keep up to 2048 boxes (R9 bug: was WIN).
__global__ __launch_bounds__(512) void k_scanw(int p)
{
    int b = blockIdx.x;
    if (g_done[b]) return;
    int t = threadIdx.x;

    extern __shared__ char dynsmem[];
    u64*    blk = (u64*)dynsmem;                       // 128KB
    float4* cbx = (float4*)(dynsmem + 131072);         // 16KB
    float*  car = (float*)(dynsmem + 131072 + 16384);  // 4KB

    __shared__ u64 rem[WRD];
    __shared__ short ckeptL[2 * WIN];                  // capacity = pair size
    __shared__ int s_kept, s_nk, s_nkc, s_nkA, s_done;

    int wbaseA = (2 * p) * WIN;
    int wbaseB = wbaseA + WIN;

    // ---- window A ----
    {
        const ulonglong2* src = (const ulonglong2*)&g_wmaskP[b][0][0][0];
        ulonglong2* dst = (ulonglong2*)blk;
#pragma unroll
        for (int q = 0; q < WRD; q++) dst[q * 512 + t] = src[q * 512 + t];
        if (t < WRD) rem[t] = g_remwP[b][0][t];
        if (t == 0) { s_kept = g_keptCnt[b]; s_done = 0; s_nkc = 0; }
        __syncthreads();

        for (int wl = 0; wl < WRD; wl++) {
            if (t == 0) {
                u64 alive = ~rem[wl];
                int nk = 0, kept = s_kept, nkc = s_nkc;
                while (alive && kept < TOPN) {
                    int j = __ffsll((long long)alive) - 1;
                    int lr = wl * 64 + j;
                    g_keptIdx[b][kept++] = wbaseA + lr;
                    ckeptL[nkc++] = (short)lr;
                    nk++;
                    alive &= ~blk[wl * WIN + lr];
                    alive &= ~(1ull << j);
                }
                s_nk = nk; s_kept = kept; s_nkc = nkc;
                if (kept >= TOPN) s_done = 1;
            }
            __syncthreads();
            if (s_done) break;
            int nk = s_nk;
            if (nk > 0 && t < WRD - 1 - wl) {
                int w2 = wl + 1 + t;
                u64 acc = rem[w2];
                int q0 = s_nkc - nk;
                for (int q = q0; q < s_nkc; q++) acc |= blk[w2 * WIN + ckeptL[q]];
                rem[w2] = acc;
            }
            __syncthreads();
        }
        if (t == 0) s_nkA = s_nkc;
        __syncthreads();
    }

    // ---- window B ----
    if (!s_done) {
        // columns of window B + base suppression
        for (int j = t; j < WIN; j += 512) {
            cbx[j] = g_sbox[b][wbaseB + j];
            car[j] = g_sarea[b][wbaseB + j];
        }
        if (t < WRD) rem[t] = g_remwP[b][1][t];
        __syncthreads();

        // delta: keeps of window A vs window B
        int nkA = s_nkA;
        for (int q = t >> 4; q < nkA; q += 32) {
            int c = wbaseA + ckeptL[q];
            float4 bi = g_sbox[b][c];
            float  ai = g_sarea[b][c];
            u64 v = iou_word(bi, ai, cbx, car, (t & 15) * 64);
            if (v) atomicOr(&rem[t & 15], v);
        }
        __syncthreads();

        const ulonglong2* src = (const ulonglong2*)&g_wmaskP[b][1][0][0];
        ulonglong2* dst = (ulonglong2*)blk;
#pragma unroll
        for (int q = 0; q < WRD; q++) dst[q * 512 + t] = src[q * 512 + t];
        __syncthreads();

        for (int wl = 0; wl < WRD; wl++) {
            if (t == 0) {
                u64 alive = ~rem[wl];
                int nk = 0, kept = s_kept, nkc = s_nkc;
                while (alive && kept < TOPN) {
                    int j = __ffsll((long long)alive) - 1;
                    int lr = wl * 64 + j;
                    g_keptIdx[b][kept++] = wbaseB + lr;
                    ckeptL[nkc++] = (short)lr;
                    nk++;
                    alive &= ~blk[wl * WIN + lr];
                    alive &= ~(1ull << j);
                }
                s_nk = nk; s_kept = kept; s_nkc = nkc;
                if (kept >= TOPN) s_done = 1;
            }
            __syncthreads();
            if (s_done) break;
            int nk = s_nk;
            if (nk > 0 && t < WRD - 1 - wl) {
                int w2 = wl + 1 + t;
                u64 acc = rem[w2];
                int q0 = s_nkc - nk;
                for (int q = q0; q < s_nkc; q++) acc |= blk[w2 * WIN + ckeptL[q]];
                rem[w2] = acc;
            }
            __syncthreads();
        }
    }

    // ---- epilogue: publish keeps for future mask launches ----
    __syncthreads();
    int nkc   = s_nkc;
    int nkA   = s_nkA;
    int kept0 = s_kept - nkc;                      // race-free base offset
    for (int q = t; q < nkc; q += 512) {
        int c = (q < nkA ? wbaseA : wbaseB) + ckeptL[q];
        g_kbox[b][kept0 + q]  = g_sbox[b][c];
        g_karea[b][kept0 + q] = g_sarea[b][c];
    }
    if (t == 0) {
        g_keptCnt[b] = s_kept;
        if (s_done) g_done[b] = 1;
    }
    if (t < 2 * WRD) g_remwP[b][t >> 4][t & 15] = 0;   // reset for next pair
}

// ----------------------------------------------------------------- out ----
__global__ __launch_bounds__(256) void k_out(float* __restrict__ out)
{
    int idx = blockIdx.x * 256 + threadIdx.x;
    if (idx >= NB * TOPN) return;
    int b = idx / TOPN;
    int r = idx - b * TOPN;
    float* o = out + (size_t)idx * 5;
    if (r < g_keptCnt[b]) {
        int c = g_keptIdx[b][r];
        float4 bx = g_sbox[b][c];
        o[0] = g_sscore[b][c];
        o[1] = bx.x; o[2] = bx.y; o[3] = bx.z; o[4] = bx.w;
    } else {
        o[0] = 0.f; o[1] = 0.f; o[2] = 0.f; o[3] = 0.f; o[4] = 0.f;
    }
}

extern "C" void kernel_launch(void* const* d_in, const int* in_sizes, int n_in,
                              void* d_out, int out_size)
{
    const float* sm  = (const float*)d_in[0];
    const float* bd  = (const float*)d_in[1];
    const float* img = (const float*)d_in[2];
    float* out = (float*)d_out;

    cudaFuncSetAttribute(k_sort_local,
                         cudaFuncAttributeMaxDynamicSharedMemorySize, 131072);
    cudaFuncSetAttribute(k_scanw,
                         cudaFuncAttributeMaxDynamicSharedMemorySize, 151552);

    k_prep<<<dim3(NPAD / 256, NB), 256>>>(sm, bd, img);

    const int nchunks = NB * NPAD / 16384;         // 8
    const size_t ssm = 131072;
    k_sort_local<<<nchunks, 1024, ssm>>>(0);
    k_sort_global<<<NB * NPAD / 256, 256>>>(32768, 16384);
    k_sort_local<<<nchunks, 1024, ssm>>>(32768);
    k_sort_global<<<NB * NPAD / 256, 256>>>(65536, 32768);
    k_sort_global<<<NB * NPAD / 256, 256>>>(65536, 16384);
    k_sort_local<<<nchunks, 1024, ssm>>>(65536);

    k_gather<<<dim3(NPROP / 256, NB), 256>>>();

    for (int p = 0; p < NPAIR; p++) {
        k_maskw<<<dim3(64, NB), 512>>>(p);
        k_scanw<<<NB, 512, 151552>>>(p);
    }

    k_out<<<(NB * TOPN + 255) / 256, 256>>>(out);
}

// round 12
// speedup vs baseline: 2.9517x; 2.2299x over previous
#include <cuda_runtime.h>
#include <cstdint>

#define NB    2
#define NA    9
#define NHW   4096        // 64*64
#define NPROP 36864       // NHW*NA
#define NPAD  65536
#define TOPN  2000
#define WIN   1024        // candidates per window
#define WRD   16          // 64-bit words per window
#define NWIN  36          // WIN*NWIN = NPROP

typedef unsigned long long u64;

// Anchors from generate_anchors(16,(0.5,1,2),(8,16,32)) with base [0,0,15,15].
__constant__ float c_anchors[9][4] = {
  { -84.f,  -40.f,  99.f,  55.f},
  {-176.f,  -88.f, 191.f, 103.f},
  {-360.f, -184.f, 375.f, 199.f},
  { -56.f,  -56.f,  71.f,  71.f},
  {-120.f, -120.f, 135.f, 135.f},
  {-248.f, -248.f, 263.f, 263.f},
  { -36.f,  -80.f,  51.f,  95.f},
  { -80.f, -168.f,  95.f, 183.f},
  {-168.f, -344.f, 183.f, 359.f}
};

__device__ float4 g_boxes [NB][NPROP];
__device__ float  g_scores[NB][NPROP];
__device__ u64    g_keys  [NB * NPAD];
__device__ float4 g_sbox  [NB][NPROP];
__device__ float  g_sscore[NB][NPROP];
__device__ float  g_sarea [NB][NPROP];
__device__ u64    g_wmask [NB][WRD][WIN];   // current window mask, [word][row]
__device__ u64    g_remw  [NB][WRD];        // kept-box suppression for window
__device__ float4 g_kbox  [NB][TOPN];       // kept boxes (for later mask phases)
__device__ float  g_karea [NB][TOPN];
__device__ int    g_keptIdx[NB][TOPN];
__device__ int    g_keptCnt[NB];
__device__ int    g_done  [NB];

// ---------------------------------------------------------------- prep ----
__global__ __launch_bounds__(256) void k_prep(const float* __restrict__ sm,
                                              const float* __restrict__ bd,
                                              const float* __restrict__ img)
{
    int b = blockIdx.y;
    int i = blockIdx.x * 256 + threadIdx.x;       // 0..NPAD-1
    if (i == 0) { g_done[b] = 0; g_keptCnt[b] = 0; }
    if (i < WRD) g_remw[b][i] = 0;
    if (i >= NPAD) return;
    if (i >= NPROP) { g_keys[b * NPAD + i] = ~0ull; return; }

    int a  = i % NA;
    int hw = i / NA;
    float cx = (float)((hw & 63) * 16 + 8);
    float cy = (float)((hw >> 6) * 16 + 8);

    float ax1 = cx + c_anchors[a][0];
    float ay1 = cy + c_anchors[a][1];
    float ax2 = cx + c_anchors[a][2];
    float ay2 = cy + c_anchors[a][3];

    float wA = ax2 - ax1 + 1.0f;                  // exact small integers
    float hA = ay2 - ay1 + 1.0f;
    float ctrx = __fadd_rn(ax1, __fmul_rn(0.5f, wA));
    float ctry = __fadd_rn(ay1, __fmul_rn(0.5f, hA));

    const float* bdb = bd + ((size_t)b * 36 + (size_t)a * 4) * NHW + hw;
    float dx = bdb[0];
    float dy = bdb[NHW];
    float dw = bdb[2 * NHW];
    float dh = bdb[3 * NHW];

    // reference op order: mul then add, no contraction
    float pcx = __fadd_rn(__fmul_rn(dx, wA), ctrx);
    float pcy = __fadd_rn(__fmul_rn(dy, hA), ctry);
    float pw  = __fmul_rn(expf(dw), wA);
    float ph  = __fmul_rn(expf(dh), hA);

    float x1 = __fsub_rn(pcx, __fmul_rn(0.5f, pw));
    float y1 = __fsub_rn(pcy, __fmul_rn(0.5f, ph));
    float x2 = __fadd_rn(pcx, __fmul_rn(0.5f, pw));
    float y2 = __fadd_rn(pcy, __fmul_rn(0.5f, ph));

    float imh = img[b * 3 + 0];
    float imw = img[b * 3 + 1];
    float mx  = __fsub_rn(imw, 1.0f);
    float my  = __fsub_rn(imh, 1.0f);
    x1 = fminf(fmaxf(x1, 0.0f), mx);
    x2 = fminf(fmaxf(x2, 0.0f), mx);
    y1 = fminf(fmaxf(y1, 0.0f), my);
    y2 = fminf(fmaxf(y2, 0.0f), my);

    float s = sm[((size_t)b * 18 + 9 + a) * NHW + hw];

    g_boxes[b][i]  = make_float4(x1, y1, x2, y2);
    g_scores[b][i] = s;

    unsigned u = __float_as_uint(s);
    unsigned k = (u & 0x80000000u) ? ~u : (u | 0x80000000u);  // ascending
    unsigned kd = ~k;                                          // descending
    g_keys[b * NPAD + i] = ((u64)kd << 32) | (unsigned)i;
}

// ---------------------------------------------------------------- sort ----
// 8192-element chunks in 64KB dynamic smem (16 blocks; measured 15.9us vs
// 27.9us for 16384). Canonical bitonic: ascending iff ((li & len) == 0).
__global__ __launch_bounds__(1024) void k_sort_local(int startLen)
{
    extern __shared__ u64 sk[];
    int base = blockIdx.x * 8192;                 // flat over NB*NPAD
    int tid  = threadIdx.x;

#pragma unroll
    for (int e = 0; e < 8; e++) sk[e * 1024 + tid] = g_keys[base + e * 1024 + tid];
    __syncthreads();

    if (startLen == 0) {
        for (int len = 2; len <= 8192; len <<= 1) {
            for (int d = len >> 1; d > 0; d >>= 1) {
#pragma unroll
                for (int e = 0; e < 4; e++) {
                    int idx = e * 1024 + tid;          // 0..4095 pair ids
                    int i = ((idx & ~(d - 1)) << 1) | (idx & (d - 1));
                    int j = i | d;
                    int li = (base + i) & (NPAD - 1);
                    bool asc = ((li & len) == 0);
                    u64 a = sk[i], c = sk[j];
                    if ((a > c) == asc) { sk[i] = c; sk[j] = a; }
                }
                __syncthreads();
            }
        }
    } else {
        bool asc = (((base & (NPAD - 1)) & startLen) == 0);
        for (int d = 4096; d > 0; d >>= 1) {
#pragma unroll
            for (int e = 0; e < 4; e++) {
                int idx = e * 1024 + tid;
                int i = ((idx & ~(d - 1)) << 1) | (idx & (d - 1));
                int j = i | d;
                u64 a = sk[i], c = sk[j];
                if ((a > c) == asc) { sk[i] = c; sk[j] = a; }
            }
            __syncthreads();
        }
    }

#pragma unroll
    for (int e = 0; e < 8; e++) g_keys[base + e * 1024 + tid] = sk[e * 1024 + tid];
}

__global__ __launch_bounds__(256) void k_sort_global(int len, int d)
{
    int i = blockIdx.x * 256 + threadIdx.x;       // flat element index
    if (i >= NB * NPAD) return;
    int li = i & (NPAD - 1);
    if (li & d) return;
    int j = i + d;                                 // same batch since (li&d)==0
    bool asc = ((li & len) == 0);
    u64 a = g_keys[i], c = g_keys[j];
    if ((a > c) == asc) { g_keys[i] = c; g_keys[j] = a; }
}

// -------------------------------------------------------------- gather ----
__global__ __launch_bounds__(256) void k_gather()
{
    int b = blockIdx.y;
    int p = blockIdx.x * 256 + threadIdx.x;
    if (p >= NPROP) return;
    unsigned idx = (unsigned)(g_keys[b * NPAD + p] & 0xFFFFFFFFull);
    float4 bx = g_boxes[b][idx];
    g_sbox[b][p]   = bx;
    g_sscore[b][p] = g_scores[b][idx];
    g_sarea[b][p]  = __fmul_rn(__fadd_rn(__fsub_rn(bx.z, bx.x), 1.0f),
                               __fadd_rn(__fsub_rn(bx.w, bx.y), 1.0f));
}

// --------------------------------------------------------- window mask ----
// Phase k: blocks 0..15 compute the 1024x1024 in-window mask rows (stored
// [word][row] for the scan's coalesced load); blocks 16..47 compute bits of
// previously-kept boxes vs the window's columns and OR them into g_remw.
// Branch-free hot loop; ambiguous IoU band resolved exactly post-loop.
__global__ __launch_bounds__(512) void k_maskw(int k)
{
    int b = blockIdx.y;
    if (g_done[b]) return;
    int bx = blockIdx.x;
    int keptCnt = g_keptCnt[b];
    if (bx >= 16 && (bx - 16) * 64 >= keptCnt) return;

    int t    = threadIdx.x;
    int rl   = t & 63;                 // row within 64-row group
    int cg   = t >> 6;                 // 0..7, each handles 2 words
    int R0   = k * WIN;

    __shared__ float4 cbx[WIN];
    __shared__ float  car[WIN];
    for (int j = t; j < WIN; j += 512) {
        cbx[j] = g_sbox[b][R0 + j];
        car[j] = g_sarea[b][R0 + j];
    }
    __shared__ u64 red[8][2];
    if (t < 16) ((u64*)red)[t] = 0;
    __syncthreads();

    float4 bi; float ai; bool active = true;
    if (bx < 16) {
        int i = R0 + bx * 64 + rl;
        bi = g_sbox[b][i];
        ai = g_sarea[b][i];
    } else {
        int kr = (bx - 16) * 64 + rl;
        active = (kr < keptCnt);
        if (active) { bi = g_kbox[b][kr]; ai = g_karea[b][kr]; }
    }

    u64 res[2];
#pragma unroll
    for (int ww = 0; ww < 2; ww++) {
        int w = cg * 2 + ww;
        int wb = w * 64;
        u64 bsup = 0, bamb = 0;
        if (active) {
#pragma unroll 8
            for (int j2 = 0; j2 < 64; j2++) {
                float4 bj = cbx[wb + j2];
                float  aj = car[wb + j2];
                float iw = fmaxf(__fadd_rn(__fsub_rn(fminf(bi.z, bj.z), fmaxf(bi.x, bj.x)), 1.0f), 0.0f);
                float ih = fmaxf(__fadd_rn(__fsub_rn(fminf(bi.w, bj.w), fmaxf(bi.y, bj.y)), 1.0f), 0.0f);
                float inter = __fmul_rn(iw, ih);
                float s     = __fadd_rn(ai, aj);
                bool hi = inter > __fmul_rn(s, 0.411775f);
                bool lo = inter < __fmul_rn(s, 0.411755f);
                bsup |= ((u64)hi) << j2;
                bamb |= ((u64)(!hi && !lo)) << j2;
            }
            while (bamb) {                         // rare exact resolution
                int j2 = __ffsll((long long)bamb) - 1;
                bamb &= bamb - 1;
                float4 bj = cbx[wb + j2];
                float iw = fmaxf(__fadd_rn(__fsub_rn(fminf(bi.z, bj.z), fmaxf(bi.x, bj.x)), 1.0f), 0.0f);
                float ih = fmaxf(__fadd_rn(__fsub_rn(fminf(bi.w, bj.w), fmaxf(bi.y, bj.y)), 1.0f), 0.0f);
                float inter = __fmul_rn(iw, ih);
                float s     = __fadd_rn(ai, car[wb + j2]);
                float denom = __fsub_rn(s, inter);
                if (__fdiv_rn(inter, denom) > 0.7f) bsup |= (1ull << j2);
            }
        }
        res[ww] = bsup;
    }

    if (bx < 16) {
        // strict-upper within own word (self + earlier lanes cleared)
#pragma unroll
        for (int ww = 0; ww < 2; ww++) {
            int w = cg * 2 + ww;
            u64 v = res[ww];
            if (w == bx) v &= (rl == 63) ? 0ull : (~0ull << (rl + 1));
            g_wmask[b][w][bx * 64 + rl] = v;
        }
    } else {
        if (active) {
            atomicOr(&red[cg][0], res[0]);
            atomicOr(&red[cg][1], res[1]);
        }
        __syncthreads();
        if (rl < 2) {
            u64 v = red[cg][rl];
            if (v) atomicOr(&g_remw[b][cg * 2 + rl], v);
        }
    }
}

// --------------------------------------------------------- window scan ----
// One block per batch. Loads the full 128KB window mask into smem, seeds rem
// with the kept-box contributions, and resolves all 16 words in shared memory
// (word-batched greedy). Appends newly-kept boxes for later mask phases.
__global__ __launch_bounds__(512) void k_scanw(int k)
{
    int b = blockIdx.x;
    if (g_done[b]) return;
    int t = threadIdx.x;
    extern __shared__ u64 blk[];                  // [WRD][WIN]
    __shared__ u64 rem[WRD];
    __shared__ short ckeptL[WIN];
    __shared__ int s_kept, s_nk, s_nkc, s_done;

    const ulonglong2* src = (const ulonglong2*)&g_wmask[b][0][0];
    ulonglong2* dst = (ulonglong2*)blk;
#pragma unroll
    for (int q = 0; q < WRD; q++) dst[q * 512 + t] = src[q * 512 + t];
    if (t < WRD) rem[t] = g_remw[b][t];
    if (t == 0) { s_kept = g_keptCnt[b]; s_done = 0; s_nkc = 0; }
    __syncthreads();

    for (int wl = 0; wl < WRD; wl++) {
        if (t == 0) {
            u64 alive = ~rem[wl];
            int nk = 0, kept = s_kept, nkc = s_nkc;
            while (alive && kept < TOPN) {
                int j = __ffsll((long long)alive) - 1;
                int lr = wl * 64 + j;
                g_keptIdx[b][kept++] = k * WIN + lr;
                ckeptL[nkc++] = (short)lr;
                nk++;
                alive &= ~blk[wl * WIN + lr];     // in-word suppression
                alive &= ~(1ull << j);
            }
            s_nk = nk; s_kept = kept; s_nkc = nkc;
            if (kept >= TOPN) s_done = 1;
        }
        __syncthreads();
        if (s_done) break;
        int nk = s_nk;
        if (nk > 0 && t < WRD - 1 - wl) {
            int w2 = wl + 1 + t;
            u64 acc = rem[w2];
            int q0 = s_nkc - nk;
            for (int q = q0; q < s_nkc; q++) acc |= blk[w2 * WIN + ckeptL[q]];
            rem[w2] = acc;
        }
        __syncthreads();
    }

    // epilogue: publish kept boxes for future mask phases
    __syncthreads();
    int nkc = s_nkc;
    int kept0 = s_kept - nkc;                     // race-free base offset
    for (int q = t; q < nkc; q += 512) {
        int c = k * WIN + ckeptL[q];
        g_kbox[b][kept0 + q]  = g_sbox[b][c];
        g_karea[b][kept0 + q] = g_sarea[b][c];
    }
    if (t == 0) {
        g_keptCnt[b] = s_kept;
        if (s_done) g_done[b] = 1;
    }
    if (t < WRD) g_remw[b][t] = 0;                // reset for next phase
}

// ----------------------------------------------------------------- out ----
__global__ __launch_bounds__(256) void k_out(float* __restrict__ out)
{
    int idx = blockIdx.x * 256 + threadIdx.x;
    if (idx >= NB * TOPN) return;
    int b = idx / TOPN;
    int r = idx - b * TOPN;
    float* o = out + (size_t)idx * 5;
    if (r < g_keptCnt[b]) {
        int c = g_keptIdx[b][r];
        float4 bx = g_sbox[b][c];
        o[0] = g_sscore[b][c];
        o[1] = bx.x; o[2] = bx.y; o[3] = bx.z; o[4] = bx.w;
    } else {
        o[0] = 0.f; o[1] = 0.f; o[2] = 0.f; o[3] = 0.f; o[4] = 0.f;
    }
}

extern "C" void kernel_launch(void* const* d_in, const int* in_sizes, int n_in,
                              void* d_out, int out_size)
{
    const float* sm  = (const float*)d_in[0];
    const float* bd  = (const float*)d_in[1];
    const float* img = (const float*)d_in[2];
    float* out = (float*)d_out;

    cudaFuncSetAttribute(k_sort_local,
                         cudaFuncAttributeMaxDynamicSharedMemorySize, 65536);
    cudaFuncSetAttribute(k_scanw,
                         cudaFuncAttributeMaxDynamicSharedMemorySize, 131072);

    k_prep<<<dim3(NPAD / 256, NB), 256>>>(sm, bd, img);

    const int nchunks = NB * NPAD / 8192;          // 16
    k_sort_local<<<nchunks, 1024, 65536>>>(0);
    k_sort_global<<<NB * NPAD / 256, 256>>>(16384, 8192);
    k_sort_local<<<nchunks, 1024, 65536>>>(16384);
    k_sort_global<<<NB * NPAD / 256, 256>>>(32768, 16384);
    k_sort_global<<<NB * NPAD / 256, 256>>>(32768, 8192);
    k_sort_local<<<nchunks, 1024, 65536>>>(32768);
    k_sort_global<<<NB * NPAD / 256, 256>>>(65536, 32768);
    k_sort_global<<<NB * NPAD / 256, 256>>>(65536, 16384);
    k_sort_global<<<NB * NPAD / 256, 256>>>(65536, 8192);
    k_sort_local<<<nchunks, 1024, 65536>>>(65536);

    k_gather<<<dim3(NPROP / 256, NB), 256>>>();

    for (int k = 0; k < NWIN; k++) {
        k_maskw<<<dim3(48, NB), 512>>>(k);
        k_scanw<<<NB, 512, 131072>>>(k);
    }

    k_out<<<(NB * TOPN + 255) / 256, 256>>>(out);
}